// round 1
// baseline (speedup 1.0000x reference)
#include <cuda_runtime.h>
#include <cuda_bf16.h>
#include <math.h>

#define BATCH 8
#define HID 128
#define TFRAMES 800
#define LSAMP 192000
#define NB 24

// frame->sample interpolation scale, matching jnp f32 semantics
#define LSCALE ((float)(800.0 / 192000.0))

// ---------------- scratch (device globals; no allocation allowed) ----------------
__device__ float g_h1[BATCH * 256 * TFRAMES];
__device__ float g_h2[BATCH * 256 * TFRAMES];
__device__ float g_band[BATCH * NB * TFRAMES];
__device__ float g_att[BATCH * TFRAMES];
__device__ float g_int[BATCH * TFRAMES];
__device__ float g_ssg[BATCH * HID * TFRAMES];
__device__ float g_ntw[BATCH * 4 * TFRAMES];
__device__ float g_filt[BATCH * LSAMP];

// ---------------- K=3 conv + leaky_relu(0.1) ----------------
// block: COUT threads, each thread = one output channel, TT time steps.
// grid.x = BATCH * (TFRAMES/TT)
template <int CIN, int COUT, int TT>
__global__ void conv3_lrelu(const float* __restrict__ x, const float* __restrict__ w,
                            const float* __restrict__ bias, float* __restrict__ y) {
    __shared__ float sx[CIN][TT + 2];
    const int ntile = TFRAMES / TT;
    const int b = blockIdx.x / ntile;
    const int t0 = (blockIdx.x % ntile) * TT;
    const int tid = threadIdx.x;

    for (int idx = tid; idx < CIN * (TT + 2); idx += COUT) {
        int ci = idx / (TT + 2);
        int tt = idx % (TT + 2);
        int t = t0 + tt - 1;
        sx[ci][tt] = (t >= 0 && t < TFRAMES) ? x[(b * CIN + ci) * TFRAMES + t] : 0.f;
    }
    __syncthreads();

    float acc[TT];
    const float bv = bias[tid];
#pragma unroll
    for (int i = 0; i < TT; i++) acc[i] = bv;

    const float* wr = w + (size_t)tid * CIN * 3;
    for (int ci = 0; ci < CIN; ci++) {
        float w0 = __ldg(&wr[ci * 3 + 0]);
        float w1 = __ldg(&wr[ci * 3 + 1]);
        float w2 = __ldg(&wr[ci * 3 + 2]);
#pragma unroll
        for (int i = 0; i < TT; i++) {
            acc[i] += w0 * sx[ci][i] + w1 * sx[ci][i + 1] + w2 * sx[ci][i + 2];
        }
    }
    float* yr = y + (size_t)(b * COUT + tid) * TFRAMES + t0;
#pragma unroll
    for (int i = 0; i < TT; i += 4) {
        float4 v;
        float a0 = acc[i + 0], a1 = acc[i + 1], a2 = acc[i + 2], a3 = acc[i + 3];
        v.x = a0 > 0.f ? a0 : 0.1f * a0;
        v.y = a1 > 0.f ? a1 : 0.1f * a1;
        v.z = a2 > 0.f ? a2 : 0.1f * a2;
        v.w = a3 > 0.f ? a3 : 0.1f * a3;
        *(float4*)(yr + i) = v;
    }
}

// ---------------- noise-predictor head: 256 -> 27, K=1, + activations ----------------
// grid = BATCH*TFRAMES blocks, 32 threads
__global__ void np_head(const float* __restrict__ h2, const float* __restrict__ w3,
                        const float* __restrict__ b3, float* __restrict__ band,
                        float* __restrict__ att, float* __restrict__ inten) {
    __shared__ float sxc[256];
    const int bt = blockIdx.x;
    const int b = bt / TFRAMES;
    const int t = bt % TFRAMES;
    const int co = threadIdx.x;
    for (int i = co; i < 256; i += 32) sxc[i] = h2[(b * 256 + i) * TFRAMES + t];
    __syncthreads();
    if (co < 27) {
        float acc = b3[co];
        const float* wr = w3 + co * 256;
#pragma unroll 8
        for (int ci = 0; ci < 256; ci++) acc += sxc[ci] * __ldg(&wr[ci]);
        float s = 1.f / (1.f + expf(-acc));
        if (co < NB) band[(b * NB + co) * TFRAMES + t] = s;
        else if (co == 24) att[b * TFRAMES + t] = s * 10.f;
        else if (co == 26) inten[b * TFRAMES + t] = s;
        // co == 25 (release) unused by reference
    }
}

// ---------------- spectral-shaper head: 128 -> 4, K=1, + softmax ----------------
__global__ void ss_head(const float* __restrict__ g, const float* __restrict__ w2,
                        const float* __restrict__ b2, float* __restrict__ ntw) {
    __shared__ float sw[4 * HID];
    const int tid = threadIdx.x;
    for (int i = tid; i < 4 * HID; i += blockDim.x) sw[i] = w2[i];
    __syncthreads();
    int idx = blockIdx.x * blockDim.x + tid;
    if (idx >= BATCH * TFRAMES) return;
    int b = idx / TFRAMES, t = idx % TFRAMES;
    float a0 = b2[0], a1 = b2[1], a2 = b2[2], a3 = b2[3];
    const float* gb = g + (size_t)b * HID * TFRAMES + t;
#pragma unroll 4
    for (int ci = 0; ci < HID; ci++) {
        float xv = gb[(size_t)ci * TFRAMES];
        a0 += xv * sw[0 * HID + ci];
        a1 += xv * sw[1 * HID + ci];
        a2 += xv * sw[2 * HID + ci];
        a3 += xv * sw[3 * HID + ci];
    }
    float m = fmaxf(fmaxf(a0, a1), fmaxf(a2, a3));
    float e0 = expf(a0 - m), e1 = expf(a1 - m), e2 = expf(a2 - m), e3 = expf(a3 - m);
    float inv = 1.f / (e0 + e1 + e2 + e3);
    ntw[(b * 4 + 0) * TFRAMES + t] = e0 * inv;
    ntw[(b * 4 + 1) * TFRAMES + t] = e1 * inv;
    ntw[(b * 4 + 2) * TFRAMES + t] = e2 * inv;
    ntw[(b * 4 + 3) * TFRAMES + t] = e3 * inv;
}

// linear interp of a frame-rate array at sample l (align_corners=False)
__device__ __forceinline__ float lin1(const float* __restrict__ a, int l) {
    float pos = ((float)l + 0.5f) * LSCALE - 0.5f;
    pos = fminf(fmaxf(pos, 0.f), (float)(TFRAMES - 1));
    int i0 = (int)pos;
    int i1 = min(i0 + 1, TFRAMES - 1);
    float fw = pos - (float)i0;
    return a[i0] * (1.f - fw) + a[i1] * fw;
}

// ---------------- noise-type filtering + mixing: filtered[b,l] ----------------
#define MIX_TILE 256
__global__ void mix_noise(const float* __restrict__ wn, const float* __restrict__ ntwf,
                          const float* __restrict__ ntw_w, float* __restrict__ filt) {
    __shared__ __align__(16) float sw[63 * 4];     // [k][f]
    __shared__ float sx[MIX_TILE + 62];
    const int b = blockIdx.y;
    const int l0 = blockIdx.x * MIX_TILE;
    const int tid = threadIdx.x;

    if (tid < 63 * 4) {
        int f = tid / 63, k = tid % 63;
        sw[k * 4 + f] = ntw_w[f * 63 + k];
    }
    for (int i = tid; i < MIX_TILE + 62; i += MIX_TILE) {
        int l = l0 + i - 31;
        sx[i] = (l >= 0 && l < LSAMP) ? wn[(size_t)b * LSAMP + l] : 0.f;
    }
    __syncthreads();

    const int l = l0 + tid;
    float a0 = 0.f, a1 = 0.f, a2 = 0.f, a3 = 0.f;
#pragma unroll
    for (int k = 0; k < 63; k++) {
        float xv = sx[tid + k];
        float4 w4 = *(const float4*)&sw[k * 4];
        a0 += xv * w4.x;
        a1 += xv * w4.y;
        a2 += xv * w4.z;
        a3 += xv * w4.w;
    }
    // linterp the 4 softmax weights
    float pos = ((float)l + 0.5f) * LSCALE - 0.5f;
    pos = fminf(fmaxf(pos, 0.f), (float)(TFRAMES - 1));
    int i0 = (int)pos;
    int i1 = min(i0 + 1, TFRAMES - 1);
    float fw = pos - (float)i0;
    const float* nb = ntwf + b * 4 * TFRAMES;
    float r = a0 * (nb[0 * TFRAMES + i0] * (1.f - fw) + nb[0 * TFRAMES + i1] * fw)
            + a1 * (nb[1 * TFRAMES + i0] * (1.f - fw) + nb[1 * TFRAMES + i1] * fw)
            + a2 * (nb[2 * TFRAMES + i0] * (1.f - fw) + nb[2 * TFRAMES + i1] * fw)
            + a3 * (nb[3 * TFRAMES + i0] * (1.f - fw) + nb[3 * TFRAMES + i1] * fw);
    filt[(size_t)b * LSAMP + l] = r;
}

// raw (pre-smoothing) gate value at sample index j (0 <= j < LSAMP)
__device__ __forceinline__ float gate_raw(const float* __restrict__ intb,
                                          const float* __restrict__ attb, int j) {
    float il = lin1(intb, j);
    float diff = (j == 0) ? 0.f : (il - lin1(intb, j - 1));
    float g = il;
    if (diff > 0.f) {
        float e = il;
        if (diff > 0.1f) e += lin1(attb, j) * 0.3f;
        e = fminf(fmaxf(e, 0.f), 1.f);
        g = e;
    }
    return g;
}

// ---------------- filter bank + band mix + gate + outputs ----------------
#define SHP_TILE 128
__global__ void shape_out(const float* __restrict__ filt, const float* __restrict__ fbw,
                          const float* __restrict__ band, const float* __restrict__ attf,
                          const float* __restrict__ intf, float* __restrict__ out,
                          int write_gate) {
    __shared__ __align__(16) float swb[31 * NB];   // [k][band]
    __shared__ float sx[SHP_TILE + 30];
    __shared__ float sgr[SHP_TILE + 4];
    const int b = blockIdx.y;
    const int l0 = blockIdx.x * SHP_TILE;
    const int tid = threadIdx.x;

    for (int i = tid; i < 31 * NB; i += SHP_TILE) {
        int k = i / NB, bd = i % NB;
        swb[i] = fbw[bd * 31 + k];
    }
    for (int i = tid; i < SHP_TILE + 30; i += SHP_TILE) {
        int l = l0 + i - 15;
        sx[i] = (l >= 0 && l < LSAMP) ? filt[(size_t)b * LSAMP + l] : 0.f;
    }
    const float* intb = intf + b * TFRAMES;
    const float* attb = attf + b * TFRAMES;
    for (int i = tid; i < SHP_TILE + 4; i += SHP_TILE) {
        int j = l0 + i - 2;
        if (j < 0) j = -j;
        if (j > LSAMP - 1) j = 2 * (LSAMP - 1) - j;
        sgr[i] = gate_raw(intb, attb, j);
    }
    __syncthreads();

    const int l = l0 + tid;
    float acc[NB];
#pragma unroll
    for (int bd = 0; bd < NB; bd++) acc[bd] = 0.f;
#pragma unroll
    for (int k = 0; k < 31; k++) {
        float xv = sx[tid + k];
#pragma unroll
        for (int q = 0; q < NB / 4; q++) {
            float4 w4 = *(const float4*)&swb[k * NB + q * 4];
            acc[q * 4 + 0] += xv * w4.x;
            acc[q * 4 + 1] += xv * w4.y;
            acc[q * 4 + 2] += xv * w4.z;
            acc[q * 4 + 3] += xv * w4.w;
        }
    }
    // band amplitude interp + mix
    float pos = ((float)l + 0.5f) * LSCALE - 0.5f;
    pos = fminf(fmaxf(pos, 0.f), (float)(TFRAMES - 1));
    int i0 = (int)pos;
    int i1 = min(i0 + 1, TFRAMES - 1);
    float fw = pos - (float)i0;
    const float* bb = band + b * NB * TFRAMES;
    float shaped = 0.f;
#pragma unroll
    for (int bd = 0; bd < NB; bd++) {
        float amp = bb[bd * TFRAMES + i0] * (1.f - fw) + bb[bd * TFRAMES + i1] * fw;
        shaped += acc[bd] * amp;
    }
    float gate = 0.2f * (sgr[tid] + sgr[tid + 1] + sgr[tid + 2] + sgr[tid + 3] + sgr[tid + 4]);
    out[(size_t)b * LSAMP + l] = shaped * gate;
    if (write_gate) out[(size_t)BATCH * LSAMP + (size_t)b * LSAMP + l] = gate;
}

// ---------------- launch ----------------
extern "C" void kernel_launch(void* const* d_in, const int* in_sizes, int n_in,
                              void* d_out, int out_size) {
    const float* cond  = (const float*)d_in[0];
    const float* wn    = (const float*)d_in[1];
    const float* np_w1 = (const float*)d_in[2];
    const float* np_b1 = (const float*)d_in[3];
    const float* np_w2 = (const float*)d_in[4];
    const float* np_b2 = (const float*)d_in[5];
    const float* np_w3 = (const float*)d_in[6];
    const float* np_b3 = (const float*)d_in[7];
    const float* ss_w1 = (const float*)d_in[8];
    const float* ss_b1 = (const float*)d_in[9];
    const float* ss_w2 = (const float*)d_in[10];
    const float* ss_b2 = (const float*)d_in[11];
    const float* fb_w  = (const float*)d_in[12];
    const float* nt_w  = (const float*)d_in[13];
    float* out = (float*)d_out;

    void *p_h1, *p_h2, *p_band, *p_att, *p_int, *p_ssg, *p_ntw, *p_filt;
    cudaGetSymbolAddress(&p_h1, g_h1);
    cudaGetSymbolAddress(&p_h2, g_h2);
    cudaGetSymbolAddress(&p_band, g_band);
    cudaGetSymbolAddress(&p_att, g_att);
    cudaGetSymbolAddress(&p_int, g_int);
    cudaGetSymbolAddress(&p_ssg, g_ssg);
    cudaGetSymbolAddress(&p_ntw, g_ntw);
    cudaGetSymbolAddress(&p_filt, g_filt);

    int write_gate = (out_size >= 2 * BATCH * LSAMP) ? 1 : 0;
    const int ntile = TFRAMES / 16;  // 50

    conv3_lrelu<128, 256, 16><<<BATCH * ntile, 256>>>(cond, np_w1, np_b1, (float*)p_h1);
    conv3_lrelu<256, 256, 16><<<BATCH * ntile, 256>>>((const float*)p_h1, np_w2, np_b2, (float*)p_h2);
    np_head<<<BATCH * TFRAMES, 32>>>((const float*)p_h2, np_w3, np_b3,
                                     (float*)p_band, (float*)p_att, (float*)p_int);
    conv3_lrelu<128, 128, 16><<<BATCH * ntile, 128>>>(cond, ss_w1, ss_b1, (float*)p_ssg);
    ss_head<<<(BATCH * TFRAMES + 255) / 256, 256>>>((const float*)p_ssg, ss_w2, ss_b2, (float*)p_ntw);
    mix_noise<<<dim3(LSAMP / MIX_TILE, BATCH), MIX_TILE>>>(wn, (const float*)p_ntw, nt_w, (float*)p_filt);
    shape_out<<<dim3(LSAMP / SHP_TILE, BATCH), SHP_TILE>>>((const float*)p_filt, fb_w,
                                                           (const float*)p_band, (const float*)p_att,
                                                           (const float*)p_int, out, write_gate);
}

// round 2
// speedup vs baseline: 2.5697x; 2.5697x over previous
#include <cuda_runtime.h>
#include <cuda_bf16.h>
#include <math.h>

#define BATCH 8
#define HID 128
#define TFRAMES 800
#define LSAMP 192000
#define NB 24
#define LSCALE ((float)(800.0 / 192000.0))

// ---------------- scratch ----------------
__device__ float g_h1[BATCH * 256 * TFRAMES];
__device__ float g_h2[BATCH * 256 * TFRAMES];
__device__ float g_band[BATCH * NB * TFRAMES];
__device__ float g_att[BATCH * TFRAMES];
__device__ float g_int[BATCH * TFRAMES];
__device__ float g_ssg[BATCH * HID * TFRAMES];
__device__ float g_ntw[BATCH * 4 * TFRAMES];
__device__ float g_filt[BATCH * LSAMP];
// transposed weights
__device__ float g_wt1[128 * 3 * 256];
__device__ float g_wt2[256 * 3 * 256];
__device__ float g_wts[128 * 3 * 128];
__device__ float g_w3t[256 * 28];
__device__ float g_w2t[128 * 4];

// ---------------- weight transposes ----------------
// w[cout][cin][3] -> wt[(ci*3+k)][cout]
__global__ void transpose_conv_w(const float* __restrict__ w, float* __restrict__ wt,
                                 int COUT, int CIN) {
    int n = COUT * CIN * 3;
    for (int idx = blockIdx.x * blockDim.x + threadIdx.x; idx < n; idx += gridDim.x * blockDim.x) {
        int co = idx / (CIN * 3);
        int rem = idx - co * (CIN * 3);
        wt[rem * COUT + co] = w[idx];
    }
}

__global__ void transpose_heads(const float* __restrict__ w3, const float* __restrict__ w2,
                                float* __restrict__ w3t, float* __restrict__ w2t) {
    int idx = blockIdx.x * blockDim.x + threadIdx.x;
    if (idx < 256 * 28) {
        int ci = idx / 28, co = idx % 28;
        w3t[idx] = (co < 27) ? w3[co * 256 + ci] : 0.f;
    }
    if (idx < 128 * 4) {
        int ci = idx / 4, f = idx % 4;
        w2t[idx] = w2[f * 128 + ci];
    }
}

// ---------------- K=3 conv + leaky_relu, GEMM-style ----------------
// tile: 64 cout x 64 t, 256 threads (16 cout-groups x 16 t-groups), 4x4 per thread
template <int CIN, int COUT>
__global__ void __launch_bounds__(256) conv3t(const float* __restrict__ x,
                                              const float* __restrict__ wt,
                                              const float* __restrict__ bias,
                                              float* __restrict__ y) {
    __shared__ float sx[32][68];
    __shared__ float swf[96 * 64];
    const int tid = threadIdx.x;
    const int cx = tid & 15, tx = tid >> 4;
    const int t_base = tx * 4, co_base = cx * 4;
    const int b = blockIdx.z, c0 = blockIdx.y * 64, t0 = blockIdx.x * 64;

    float a[4][4];
    const float4 bv = *(const float4*)&bias[c0 + co_base];
    const float bvv[4] = {bv.x, bv.y, bv.z, bv.w};
#pragma unroll
    for (int j = 0; j < 4; j++)
#pragma unroll
        for (int i = 0; i < 4; i++) a[j][i] = bvv[j];

    for (int ci0 = 0; ci0 < CIN; ci0 += 32) {
#pragma unroll 1
        for (int idx = tid; idx < 32 * 66; idx += 256) {
            int kc = idx / 66, i = idx - kc * 66;
            int t = t0 + i - 1;
            sx[kc][i] = (t >= 0 && t < TFRAMES)
                            ? x[((size_t)(b * CIN + ci0 + kc)) * TFRAMES + t] : 0.f;
        }
#pragma unroll 1
        for (int idx = tid; idx < 6144; idx += 256) {
            swf[idx] = wt[(size_t)(ci0 * 3 + (idx >> 6)) * COUT + c0 + (idx & 63)];
        }
        __syncthreads();
#pragma unroll 8
        for (int kc = 0; kc < 32; kc++) {
            const float* xr = &sx[kc][t_base];
            float4 xa = *(const float4*)xr;
            float2 xb = *(const float2*)(xr + 4);
            float xv[6] = {xa.x, xa.y, xa.z, xa.w, xb.x, xb.y};
            const float* wr = &swf[kc * 192 + co_base];
            float4 w0 = *(const float4*)wr;
            float4 w1 = *(const float4*)(wr + 64);
            float4 w2 = *(const float4*)(wr + 128);
            float wv0[4] = {w0.x, w0.y, w0.z, w0.w};
            float wv1[4] = {w1.x, w1.y, w1.z, w1.w};
            float wv2[4] = {w2.x, w2.y, w2.z, w2.w};
#pragma unroll
            for (int j = 0; j < 4; j++)
#pragma unroll
                for (int i = 0; i < 4; i++)
                    a[j][i] += wv0[j] * xv[i] + wv1[j] * xv[i + 1] + wv2[j] * xv[i + 2];
        }
        __syncthreads();
    }

    const int t_out = t0 + t_base;
#pragma unroll
    for (int j = 0; j < 4; j++) {
        float v[4];
#pragma unroll
        for (int i = 0; i < 4; i++) {
            float q = a[j][i];
            v[i] = q > 0.f ? q : 0.1f * q;
        }
        float* yr = y + ((size_t)(b * COUT + c0 + co_base + j)) * TFRAMES + t_out;
        if (t_out + 3 < TFRAMES) {
            float4 o = {v[0], v[1], v[2], v[3]};
            *(float4*)yr = o;
        } else {
#pragma unroll
            for (int i = 0; i < 4; i++)
                if (t_out + i < TFRAMES) yr[i] = v[i];
        }
    }
}

// ---------------- noise-predictor head: 256 -> 27 ----------------
__global__ void __launch_bounds__(128) np_head2(const float* __restrict__ h2,
                                                const float* __restrict__ w3t,
                                                const float* __restrict__ b3,
                                                float* __restrict__ band,
                                                float* __restrict__ att,
                                                float* __restrict__ inten) {
    __shared__ float swh[256 * 28];
    __shared__ float sb[28];
    const int tid = threadIdx.x;
    for (int i = tid; i < 256 * 28; i += 128) swh[i] = w3t[i];
    if (tid < 28) sb[tid] = (tid < 27) ? b3[tid] : 0.f;
    __syncthreads();
    const int b = blockIdx.y;
    const int t = blockIdx.x * 128 + tid;
    if (t >= TFRAMES) return;

    float acc[28];
#pragma unroll
    for (int q = 0; q < 28; q++) acc[q] = sb[q];
    const float* xp = h2 + ((size_t)b * 256) * TFRAMES + t;
#pragma unroll 4
    for (int ci = 0; ci < 256; ci++) {
        float xv = __ldg(xp + (size_t)ci * TFRAMES);
        const float* wr = &swh[ci * 28];
#pragma unroll
        for (int q = 0; q < 7; q++) {
            float4 w = *(const float4*)&wr[q * 4];
            acc[q * 4 + 0] += xv * w.x;
            acc[q * 4 + 1] += xv * w.y;
            acc[q * 4 + 2] += xv * w.z;
            acc[q * 4 + 3] += xv * w.w;
        }
    }
#pragma unroll
    for (int co = 0; co < 27; co++) {
        float s = 1.f / (1.f + expf(-acc[co]));
        if (co < NB) band[(size_t)(b * NB + co) * TFRAMES + t] = s;
        else if (co == 24) att[b * TFRAMES + t] = s * 10.f;
        else if (co == 26) inten[b * TFRAMES + t] = s;
    }
}

// ---------------- spectral-shaper head: 128 -> 4 + softmax ----------------
__global__ void ss_head2(const float* __restrict__ g, const float* __restrict__ w2t,
                         const float* __restrict__ b2, float* __restrict__ ntw) {
    __shared__ float sw[512];
    const int tid = threadIdx.x;
    for (int i = tid; i < 512; i += 256) sw[i] = w2t[i];
    __syncthreads();
    int idx = blockIdx.x * 256 + tid;
    if (idx >= BATCH * TFRAMES) return;
    int b = idx / TFRAMES, t = idx - b * TFRAMES;
    float a0 = b2[0], a1 = b2[1], a2 = b2[2], a3 = b2[3];
    const float* gb = g + (size_t)b * HID * TFRAMES + t;
#pragma unroll 4
    for (int ci = 0; ci < HID; ci++) {
        float xv = __ldg(gb + (size_t)ci * TFRAMES);
        float4 w = *(const float4*)&sw[ci * 4];
        a0 += xv * w.x; a1 += xv * w.y; a2 += xv * w.z; a3 += xv * w.w;
    }
    float m = fmaxf(fmaxf(a0, a1), fmaxf(a2, a3));
    float e0 = expf(a0 - m), e1 = expf(a1 - m), e2 = expf(a2 - m), e3 = expf(a3 - m);
    float inv = 1.f / (e0 + e1 + e2 + e3);
    ntw[(size_t)(b * 4 + 0) * TFRAMES + t] = e0 * inv;
    ntw[(size_t)(b * 4 + 1) * TFRAMES + t] = e1 * inv;
    ntw[(size_t)(b * 4 + 2) * TFRAMES + t] = e2 * inv;
    ntw[(size_t)(b * 4 + 3) * TFRAMES + t] = e3 * inv;
}

// interp from staged smem frames
__device__ __forceinline__ float lin1s(const float* __restrict__ s, int j, int f0) {
    float pos = ((float)j + 0.5f) * LSCALE - 0.5f;
    pos = fminf(fmaxf(pos, 0.f), (float)(TFRAMES - 1));
    int i0 = (int)pos;
    int i1 = min(i0 + 1, TFRAMES - 1);
    float fw = pos - (float)i0;
    return s[i0 - f0] * (1.f - fw) + s[i1 - f0] * fw;
}

// ---------------- noise-type filtering + mixing ----------------
#define MTILE 512
__global__ void __launch_bounds__(128) mix_noise2(const float* __restrict__ wn,
                                                  const float* __restrict__ ntwf,
                                                  const float* __restrict__ ntw_w,
                                                  float* __restrict__ filt) {
    __shared__ __align__(16) float sw4[63 * 4];
    __shared__ float sx[MTILE + 64];
    __shared__ float sn[4 * 8];
    const int b = blockIdx.y;
    const int l0 = blockIdx.x * MTILE;
    const int tid = threadIdx.x;

    for (int i = tid; i < 252; i += 128) {
        int f = i / 63, k = i - f * 63;
        sw4[k * 4 + f] = ntw_w[i];
    }
    for (int i = tid; i < MTILE + 62; i += 128) {
        int l = l0 + i - 31;
        sx[i] = (l >= 0 && l < LSAMP) ? wn[(size_t)b * LSAMP + l] : 0.f;
    }
    const int f0 = max(0, (int)floorf((l0 + 0.5f) * LSCALE - 0.5f));
    if (tid < 32) {
        int f = tid / 8, fi = tid & 7;
        sn[tid] = ntwf[(size_t)(b * 4 + f) * TFRAMES + min(f0 + fi, TFRAMES - 1)];
    }
    __syncthreads();

    const int ts = tid * 4;
    float a[4][4];
#pragma unroll
    for (int f = 0; f < 4; f++)
#pragma unroll
        for (int i = 0; i < 4; i++) a[f][i] = 0.f;

    float x0 = sx[ts], x1 = sx[ts + 1], x2 = sx[ts + 2], x3;
#pragma unroll 7
    for (int k = 0; k < 63; k++) {
        x3 = sx[ts + k + 3];
        float4 w = *(const float4*)&sw4[k * 4];
        a[0][0] += w.x * x0; a[0][1] += w.x * x1; a[0][2] += w.x * x2; a[0][3] += w.x * x3;
        a[1][0] += w.y * x0; a[1][1] += w.y * x1; a[1][2] += w.y * x2; a[1][3] += w.y * x3;
        a[2][0] += w.z * x0; a[2][1] += w.z * x1; a[2][2] += w.z * x2; a[2][3] += w.z * x3;
        a[3][0] += w.w * x0; a[3][1] += w.w * x1; a[3][2] += w.w * x2; a[3][3] += w.w * x3;
        x0 = x1; x1 = x2; x2 = x3;
    }
    float res[4];
#pragma unroll
    for (int i = 0; i < 4; i++) {
        int l = l0 + ts + i;
        float pos = ((float)l + 0.5f) * LSCALE - 0.5f;
        pos = fminf(fmaxf(pos, 0.f), (float)(TFRAMES - 1));
        int i0 = (int)pos;
        int i1 = min(i0 + 1, TFRAMES - 1);
        float fw = pos - (float)i0;
        int fa = i0 - f0, fb = i1 - f0;
        res[i] = a[0][i] * (sn[0 * 8 + fa] * (1.f - fw) + sn[0 * 8 + fb] * fw)
               + a[1][i] * (sn[1 * 8 + fa] * (1.f - fw) + sn[1 * 8 + fb] * fw)
               + a[2][i] * (sn[2 * 8 + fa] * (1.f - fw) + sn[2 * 8 + fb] * fw)
               + a[3][i] * (sn[3 * 8 + fa] * (1.f - fw) + sn[3 * 8 + fb] * fw);
    }
    float4 o = {res[0], res[1], res[2], res[3]};
    *(float4*)&filt[(size_t)b * LSAMP + l0 + ts] = o;
}

// ---------------- filter bank + band mix + gate + outputs ----------------
#define STILE 512
__global__ void __launch_bounds__(128) shape_out2(const float* __restrict__ filt,
                                                  const float* __restrict__ fbw,
                                                  const float* __restrict__ band,
                                                  const float* __restrict__ attf,
                                                  const float* __restrict__ intf,
                                                  float* __restrict__ out, int write_gate) {
    __shared__ __align__(16) float swb[31 * 24];
    __shared__ float sx[STILE + 32];
    __shared__ float sgr[STILE + 4];
    __shared__ float sband[24 * 8];
    __shared__ float sia[16];  // [0..7]=intensity frames, [8..15]=attack frames
    const int b = blockIdx.y;
    const int l0 = blockIdx.x * STILE;
    const int tid = threadIdx.x;

    for (int i = tid; i < 31 * 24; i += 128) {
        int k = i / 24, bd = i - k * 24;
        swb[i] = fbw[bd * 31 + k];
    }
    for (int i = tid; i < STILE + 30; i += 128) {
        int l = l0 + i - 15;
        sx[i] = (l >= 0 && l < LSAMP) ? filt[(size_t)b * LSAMP + l] : 0.f;
    }
    const int fb0 = max(0, (int)floorf((l0 + 0.5f) * LSCALE - 0.5f));
    for (int i = tid; i < 24 * 8; i += 128) {
        int bd = i / 8, fi = i & 7;
        sband[i] = band[(size_t)(b * NB + bd) * TFRAMES + min(fb0 + fi, TFRAMES - 1)];
    }
    const int fg0 = max(0, (int)floorf((l0 - 2.5f) * LSCALE - 0.5f));
    if (tid < 16) {
        int fi = tid & 7;
        int fr = min(fg0 + fi, TFRAMES - 1);
        sia[tid] = (tid < 8) ? intf[b * TFRAMES + fr] : attf[b * TFRAMES + fr];
    }
    __syncthreads();

    // raw gate into sgr (needs sia staged)
    for (int i = tid; i < STILE + 4; i += 128) {
        int j = l0 + i - 2;
        if (j < 0) j = -j;
        if (j > LSAMP - 1) j = 2 * (LSAMP - 1) - j;
        float il = lin1s(sia, j, fg0);
        float diff = (j == 0) ? 0.f : (il - lin1s(sia, j - 1, fg0));
        float gv = il;
        if (diff > 0.f) {
            float e = il;
            if (diff > 0.1f) e += lin1s(&sia[8], j, fg0) * 0.3f;
            gv = fminf(fmaxf(e, 0.f), 1.f);
        }
        sgr[i] = gv;
    }
    __syncthreads();

    const int ts = tid * 4;
    float fw4[4];
    int fiA[4], fiB[4];
#pragma unroll
    for (int i = 0; i < 4; i++) {
        int l = l0 + ts + i;
        float pos = ((float)l + 0.5f) * LSCALE - 0.5f;
        pos = fminf(fmaxf(pos, 0.f), (float)(TFRAMES - 1));
        int i0 = (int)pos;
        int i1 = min(i0 + 1, TFRAMES - 1);
        fw4[i] = pos - (float)i0;
        fiA[i] = i0 - fb0;
        fiB[i] = i1 - fb0;
    }

    float shaped[4] = {0.f, 0.f, 0.f, 0.f};
#pragma unroll 1
    for (int g3 = 0; g3 < 3; g3++) {
        float a[8][4];
#pragma unroll
        for (int bd = 0; bd < 8; bd++)
#pragma unroll
            for (int i = 0; i < 4; i++) a[bd][i] = 0.f;
        float x0 = sx[ts], x1 = sx[ts + 1], x2 = sx[ts + 2], x3;
#pragma unroll
        for (int k = 0; k < 31; k++) {
            x3 = sx[ts + k + 3];
            const float* wr = &swb[k * 24 + g3 * 8];
            float4 wA = *(const float4*)wr;
            float4 wB = *(const float4*)(wr + 4);
            float wv[8] = {wA.x, wA.y, wA.z, wA.w, wB.x, wB.y, wB.z, wB.w};
#pragma unroll
            for (int bd = 0; bd < 8; bd++) {
                a[bd][0] += wv[bd] * x0;
                a[bd][1] += wv[bd] * x1;
                a[bd][2] += wv[bd] * x2;
                a[bd][3] += wv[bd] * x3;
            }
            x0 = x1; x1 = x2; x2 = x3;
        }
#pragma unroll
        for (int bd = 0; bd < 8; bd++) {
            const float* sb8 = &sband[(g3 * 8 + bd) * 8];
#pragma unroll
            for (int i = 0; i < 4; i++) {
                float amp = sb8[fiA[i]] * (1.f - fw4[i]) + sb8[fiB[i]] * fw4[i];
                shaped[i] += a[bd][i] * amp;
            }
        }
    }

    float s[8];
#pragma unroll
    for (int ii = 0; ii < 8; ii++) s[ii] = sgr[ts + ii];
    float4 og, oo;
    float gv0 = 0.2f * (s[0] + s[1] + s[2] + s[3] + s[4]);
    float gv1 = 0.2f * (s[1] + s[2] + s[3] + s[4] + s[5]);
    float gv2 = 0.2f * (s[2] + s[3] + s[4] + s[5] + s[6]);
    float gv3 = 0.2f * (s[3] + s[4] + s[5] + s[6] + s[7]);
    og = make_float4(gv0, gv1, gv2, gv3);
    oo = make_float4(shaped[0] * gv0, shaped[1] * gv1, shaped[2] * gv2, shaped[3] * gv3);
    *(float4*)&out[(size_t)b * LSAMP + l0 + ts] = oo;
    if (write_gate)
        *(float4*)&out[(size_t)BATCH * LSAMP + (size_t)b * LSAMP + l0 + ts] = og;
}

// ---------------- launch ----------------
extern "C" void kernel_launch(void* const* d_in, const int* in_sizes, int n_in,
                              void* d_out, int out_size) {
    const float* cond  = (const float*)d_in[0];
    const float* wn    = (const float*)d_in[1];
    const float* np_w1 = (const float*)d_in[2];
    const float* np_b1 = (const float*)d_in[3];
    const float* np_w2 = (const float*)d_in[4];
    const float* np_b2 = (const float*)d_in[5];
    const float* np_w3 = (const float*)d_in[6];
    const float* np_b3 = (const float*)d_in[7];
    const float* ss_w1 = (const float*)d_in[8];
    const float* ss_b1 = (const float*)d_in[9];
    const float* ss_w2 = (const float*)d_in[10];
    const float* ss_b2 = (const float*)d_in[11];
    const float* fb_w  = (const float*)d_in[12];
    const float* nt_w  = (const float*)d_in[13];
    float* out = (float*)d_out;

    void *p_h1, *p_h2, *p_band, *p_att, *p_int, *p_ssg, *p_ntw, *p_filt;
    void *p_wt1, *p_wt2, *p_wts, *p_w3t, *p_w2t;
    cudaGetSymbolAddress(&p_h1, g_h1);
    cudaGetSymbolAddress(&p_h2, g_h2);
    cudaGetSymbolAddress(&p_band, g_band);
    cudaGetSymbolAddress(&p_att, g_att);
    cudaGetSymbolAddress(&p_int, g_int);
    cudaGetSymbolAddress(&p_ssg, g_ssg);
    cudaGetSymbolAddress(&p_ntw, g_ntw);
    cudaGetSymbolAddress(&p_filt, g_filt);
    cudaGetSymbolAddress(&p_wt1, g_wt1);
    cudaGetSymbolAddress(&p_wt2, g_wt2);
    cudaGetSymbolAddress(&p_wts, g_wts);
    cudaGetSymbolAddress(&p_w3t, g_w3t);
    cudaGetSymbolAddress(&p_w2t, g_w2t);

    int write_gate = (out_size >= 2 * BATCH * LSAMP) ? 1 : 0;

    transpose_conv_w<<<384, 256>>>(np_w1, (float*)p_wt1, 256, 128);
    transpose_conv_w<<<768, 256>>>(np_w2, (float*)p_wt2, 256, 256);
    transpose_conv_w<<<192, 256>>>(ss_w1, (float*)p_wts, 128, 128);
    transpose_heads<<<28, 256>>>(np_w3, ss_w2, (float*)p_w3t, (float*)p_w2t);

    conv3t<128, 256><<<dim3(13, 4, BATCH), 256>>>(cond, (const float*)p_wt1, np_b1, (float*)p_h1);
    conv3t<256, 256><<<dim3(13, 4, BATCH), 256>>>((const float*)p_h1, (const float*)p_wt2, np_b2, (float*)p_h2);
    np_head2<<<dim3(7, BATCH), 128>>>((const float*)p_h2, (const float*)p_w3t, np_b3,
                                      (float*)p_band, (float*)p_att, (float*)p_int);
    conv3t<128, 128><<<dim3(13, 2, BATCH), 256>>>(cond, (const float*)p_wts, ss_b1, (float*)p_ssg);
    ss_head2<<<25, 256>>>((const float*)p_ssg, (const float*)p_w2t, ss_b2, (float*)p_ntw);
    mix_noise2<<<dim3(LSAMP / MTILE, BATCH), 128>>>(wn, (const float*)p_ntw, nt_w, (float*)p_filt);
    shape_out2<<<dim3(LSAMP / STILE, BATCH), 128>>>((const float*)p_filt, fb_w,
                                                    (const float*)p_band, (const float*)p_att,
                                                    (const float*)p_int, out, write_gate);
}

// round 3
// speedup vs baseline: 2.7417x; 1.0669x over previous
#include <cuda_runtime.h>
#include <cuda_bf16.h>
#include <math.h>

#define BATCH 8
#define HID 128
#define TFRAMES 800
#define LSAMP 192000
#define NB 24
#define LSCALE ((float)(800.0 / 192000.0))

typedef unsigned long long ull;

// ---- packed fp32x2 helpers (FFMA2 path; ptxas never auto-generates these) ----
__device__ __forceinline__ ull pk2(float lo, float hi) {
    ull r; asm("mov.b64 %0, {%1, %2};" : "=l"(r) : "f"(lo), "f"(hi)); return r;
}
__device__ __forceinline__ ull dup2(float v) {
    ull r; asm("mov.b64 %0, {%1, %1};" : "=l"(r) : "f"(v)); return r;
}
__device__ __forceinline__ void fma2(ull& acc, ull a, ull b) {
    asm("fma.rn.f32x2 %0, %1, %2, %0;" : "+l"(acc) : "l"(a), "l"(b));
}
__device__ __forceinline__ float2 upk2(ull v) {
    float2 f; asm("mov.b64 {%0, %1}, %2;" : "=f"(f.x), "=f"(f.y) : "l"(v)); return f;
}

// ---------------- scratch ----------------
__device__ float g_h1[BATCH * 256 * TFRAMES];
__device__ float g_h2[BATCH * 256 * TFRAMES];
__device__ float g_band[BATCH * NB * TFRAMES];
__device__ float g_att[BATCH * TFRAMES];
__device__ float g_int[BATCH * TFRAMES];
__device__ float g_ssg[BATCH * HID * TFRAMES];
__device__ float g_ntw[BATCH * 4 * TFRAMES];
__device__ float g_filt[BATCH * LSAMP];
__device__ float g_wt1[128 * 3 * 256];
__device__ float g_wt2[256 * 3 * 256];
__device__ float g_wts[128 * 3 * 128];
__device__ float g_w3t[256 * 28];
__device__ float g_w2t[128 * 4];

// ---------------- fused weight prep (one kernel) ----------------
// conv w[cout][cin][3] -> wt[(ci*3+k)][cout]; head transposes
__global__ void prep_weights(const float* __restrict__ w1, const float* __restrict__ w2,
                             const float* __restrict__ ws, const float* __restrict__ w3,
                             const float* __restrict__ wss2,
                             float* __restrict__ wt1, float* __restrict__ wt2,
                             float* __restrict__ wts, float* __restrict__ w3t,
                             float* __restrict__ w2t) {
    const int N1 = 256 * 128 * 3, N2 = 256 * 256 * 3, NS = 128 * 128 * 3;
    const int N3 = 256 * 28, N4 = 128 * 4;
    int total = N1 + N2 + NS + N3 + N4;
    for (int idx = blockIdx.x * blockDim.x + threadIdx.x; idx < total;
         idx += gridDim.x * blockDim.x) {
        int i = idx;
        if (i < N1) {
            int co = i / (128 * 3), rem = i - co * (128 * 3);
            wt1[rem * 256 + co] = w1[i];
        } else if ((i -= N1) < N2) {
            int co = i / (256 * 3), rem = i - co * (256 * 3);
            wt2[rem * 256 + co] = w2[i];
        } else if ((i -= N2) < NS) {
            int co = i / (128 * 3), rem = i - co * (128 * 3);
            wts[rem * 128 + co] = ws[i];
        } else if ((i -= NS) < N3) {
            int ci = i / 28, co = i - ci * 28;
            w3t[i] = (co < 27) ? w3[co * 256 + ci] : 0.f;
        } else {
            i -= N3;
            int ci = i / 4, f = i - ci * 4;
            w2t[i] = wss2[f * 128 + ci];
        }
    }
}

// ---------------- K=3 conv + leaky_relu, GEMM-style, f32x2 ----------------
// tile: 64 cout x 64 t, 256 threads, thread = 4 cout (2 pairs) x 4 t
template <int CIN, int COUT>
__global__ void __launch_bounds__(256) conv3t(const float* __restrict__ x,
                                              const float* __restrict__ wt,
                                              const float* __restrict__ bias,
                                              float* __restrict__ y) {
    __shared__ __align__(16) float sx[32][68];
    __shared__ __align__(16) float swf[96 * 64];
    const int tid = threadIdx.x;
    const int cx = tid & 15, tx = tid >> 4;
    const int t_base = tx * 4, co_base = cx * 4;
    const int b = blockIdx.z, c0 = blockIdx.y * 64, t0 = blockIdx.x * 64;

    ull acc[2][4];  // [cout-pair][t]
    {
        const float4 bv = *(const float4*)&bias[c0 + co_base];
        ull p0 = pk2(bv.x, bv.y), p1 = pk2(bv.z, bv.w);
#pragma unroll
        for (int i = 0; i < 4; i++) { acc[0][i] = p0; acc[1][i] = p1; }
    }

    for (int ci0 = 0; ci0 < CIN; ci0 += 32) {
#pragma unroll 1
        for (int idx = tid; idx < 32 * 66; idx += 256) {
            int kc = idx / 66, i = idx - kc * 66;
            int t = t0 + i - 1;
            sx[kc][i] = (t >= 0 && t < TFRAMES)
                            ? x[((size_t)(b * CIN + ci0 + kc)) * TFRAMES + t] : 0.f;
        }
#pragma unroll 1
        for (int idx = tid; idx < 6144; idx += 256) {
            swf[idx] = wt[(size_t)(ci0 * 3 + (idx >> 6)) * COUT + c0 + (idx & 63)];
        }
        __syncthreads();
#pragma unroll 4
        for (int kc = 0; kc < 32; kc++) {
            const float* xr = &sx[kc][t_base];
            float4 xa = *(const float4*)xr;
            float2 xb = *(const float2*)(xr + 4);
            ull xd[6];
            xd[0] = dup2(xa.x); xd[1] = dup2(xa.y); xd[2] = dup2(xa.z);
            xd[3] = dup2(xa.w); xd[4] = dup2(xb.x); xd[5] = dup2(xb.y);
            const ull* w0 = (const ull*)&swf[kc * 192 + co_base];
            const ull* w1 = (const ull*)&swf[kc * 192 + 64 + co_base];
            const ull* w2 = (const ull*)&swf[kc * 192 + 128 + co_base];
#pragma unroll
            for (int jp = 0; jp < 2; jp++) {
                ull wa = w0[jp], wb = w1[jp], wc = w2[jp];
#pragma unroll
                for (int i = 0; i < 4; i++) {
                    fma2(acc[jp][i], wa, xd[i]);
                    fma2(acc[jp][i], wb, xd[i + 1]);
                    fma2(acc[jp][i], wc, xd[i + 2]);
                }
            }
        }
        __syncthreads();
    }

    const int t_out = t0 + t_base;
#pragma unroll
    for (int jp = 0; jp < 2; jp++) {
        float vlo[4], vhi[4];
#pragma unroll
        for (int i = 0; i < 4; i++) {
            float2 f = upk2(acc[jp][i]);
            vlo[i] = f.x > 0.f ? f.x : 0.1f * f.x;
            vhi[i] = f.y > 0.f ? f.y : 0.1f * f.y;
        }
        float* yr0 = y + ((size_t)(b * COUT + c0 + co_base + jp * 2)) * TFRAMES + t_out;
        float* yr1 = yr0 + TFRAMES;
        if (t_out + 3 < TFRAMES) {
            *(float4*)yr0 = make_float4(vlo[0], vlo[1], vlo[2], vlo[3]);
            *(float4*)yr1 = make_float4(vhi[0], vhi[1], vhi[2], vhi[3]);
        } else {
#pragma unroll
            for (int i = 0; i < 4; i++)
                if (t_out + i < TFRAMES) { yr0[i] = vlo[i]; yr1[i] = vhi[i]; }
        }
    }
}

// ---------------- noise-predictor head: 256 -> 27, f32x2 ----------------
__global__ void __launch_bounds__(128) np_head2(const float* __restrict__ h2,
                                                const float* __restrict__ w3t,
                                                const float* __restrict__ b3,
                                                float* __restrict__ band,
                                                float* __restrict__ att,
                                                float* __restrict__ inten) {
    __shared__ __align__(16) float swh[256 * 28];
    const int tid = threadIdx.x;
    for (int i = tid; i < 256 * 28; i += 128) swh[i] = w3t[i];
    __syncthreads();
    const int b = blockIdx.y;
    const int t = blockIdx.x * 128 + tid;
    if (t >= TFRAMES) return;

    ull acc[14];
#pragma unroll
    for (int q = 0; q < 13; q++) acc[q] = pk2(b3[2 * q], b3[2 * q + 1]);
    acc[13] = pk2(b3[26], 0.f);
    const float* xp = h2 + ((size_t)b * 256) * TFRAMES + t;
#pragma unroll 2
    for (int ci = 0; ci < 256; ci++) {
        ull xd = dup2(__ldg(xp + (size_t)ci * TFRAMES));
        const ull* wr = (const ull*)&swh[ci * 28];
#pragma unroll
        for (int q = 0; q < 14; q++) fma2(acc[q], wr[q], xd);
    }
    float* bb = band + (size_t)b * NB * TFRAMES + t;
#pragma unroll
    for (int q = 0; q < 12; q++) {
        float2 f = upk2(acc[q]);
        bb[(size_t)(2 * q) * TFRAMES] = 1.f / (1.f + expf(-f.x));
        bb[(size_t)(2 * q + 1) * TFRAMES] = 1.f / (1.f + expf(-f.y));
    }
    float2 fA = upk2(acc[12]);  // co 24 (attack), 25 (release, unused)
    float2 fI = upk2(acc[13]);  // co 26 (intensity)
    att[b * TFRAMES + t] = 10.f / (1.f + expf(-fA.x));
    inten[b * TFRAMES + t] = 1.f / (1.f + expf(-fI.x));
}

// ---------------- spectral-shaper head: 128 -> 4 + softmax ----------------
__global__ void ss_head2(const float* __restrict__ g, const float* __restrict__ w2t,
                         const float* __restrict__ b2, float* __restrict__ ntw) {
    __shared__ __align__(16) float sw[512];
    const int tid = threadIdx.x;
    for (int i = tid; i < 512; i += 256) sw[i] = w2t[i];
    __syncthreads();
    int idx = blockIdx.x * 256 + tid;
    if (idx >= BATCH * TFRAMES) return;
    int b = idx / TFRAMES, t = idx - b * TFRAMES;
    ull a01 = pk2(b2[0], b2[1]), a23 = pk2(b2[2], b2[3]);
    const float* gb = g + (size_t)b * HID * TFRAMES + t;
#pragma unroll 4
    for (int ci = 0; ci < HID; ci++) {
        ull xd = dup2(__ldg(gb + (size_t)ci * TFRAMES));
        const ull* wr = (const ull*)&sw[ci * 4];
        fma2(a01, wr[0], xd);
        fma2(a23, wr[1], xd);
    }
    float2 f01 = upk2(a01), f23 = upk2(a23);
    float m = fmaxf(fmaxf(f01.x, f01.y), fmaxf(f23.x, f23.y));
    float e0 = expf(f01.x - m), e1 = expf(f01.y - m);
    float e2 = expf(f23.x - m), e3 = expf(f23.y - m);
    float inv = 1.f / (e0 + e1 + e2 + e3);
    ntw[(size_t)(b * 4 + 0) * TFRAMES + t] = e0 * inv;
    ntw[(size_t)(b * 4 + 1) * TFRAMES + t] = e1 * inv;
    ntw[(size_t)(b * 4 + 2) * TFRAMES + t] = e2 * inv;
    ntw[(size_t)(b * 4 + 3) * TFRAMES + t] = e3 * inv;
}

__device__ __forceinline__ float lin1s(const float* __restrict__ s, int j, int f0) {
    float pos = ((float)j + 0.5f) * LSCALE - 0.5f;
    pos = fminf(fmaxf(pos, 0.f), (float)(TFRAMES - 1));
    int i0 = (int)pos;
    int i1 = min(i0 + 1, TFRAMES - 1);
    float fw = pos - (float)i0;
    return s[i0 - f0] * (1.f - fw) + s[i1 - f0] * fw;
}

// ---------------- noise-type filtering + mixing, f32x2 ----------------
#define MTILE 512
__global__ void __launch_bounds__(128) mix_noise2(const float* __restrict__ wn,
                                                  const float* __restrict__ ntwf,
                                                  const float* __restrict__ ntw_w,
                                                  float* __restrict__ filt) {
    __shared__ __align__(16) float sw4[63 * 4];
    __shared__ float sx[MTILE + 64];
    __shared__ float sn[4 * 8];
    const int b = blockIdx.y;
    const int l0 = blockIdx.x * MTILE;
    const int tid = threadIdx.x;

    for (int i = tid; i < 252; i += 128) {
        int f = i / 63, k = i - f * 63;
        sw4[k * 4 + f] = ntw_w[i];
    }
    for (int i = tid; i < MTILE + 62; i += 128) {
        int l = l0 + i - 31;
        sx[i] = (l >= 0 && l < LSAMP) ? wn[(size_t)b * LSAMP + l] : 0.f;
    }
    const int f0 = max(0, (int)floorf((l0 + 0.5f) * LSCALE - 0.5f));
    if (tid < 32) {
        int f = tid / 8, fi = tid & 7;
        sn[tid] = ntwf[(size_t)(b * 4 + f) * TFRAMES + min(f0 + fi, TFRAMES - 1)];
    }
    __syncthreads();

    const int ts = tid * 4;
    ull a2[2][4];  // [filter-pair][sample]
#pragma unroll
    for (int p = 0; p < 2; p++)
#pragma unroll
        for (int i = 0; i < 4; i++) a2[p][i] = 0ull;

    ull xd0 = dup2(sx[ts]), xd1 = dup2(sx[ts + 1]), xd2 = dup2(sx[ts + 2]), xd3;
#pragma unroll 7
    for (int k = 0; k < 63; k++) {
        xd3 = dup2(sx[ts + k + 3]);
        const ull* wr = (const ull*)&sw4[k * 4];
        ull w01 = wr[0], w23 = wr[1];
        fma2(a2[0][0], w01, xd0); fma2(a2[0][1], w01, xd1);
        fma2(a2[0][2], w01, xd2); fma2(a2[0][3], w01, xd3);
        fma2(a2[1][0], w23, xd0); fma2(a2[1][1], w23, xd1);
        fma2(a2[1][2], w23, xd2); fma2(a2[1][3], w23, xd3);
        xd0 = xd1; xd1 = xd2; xd2 = xd3;
    }
    float res[4];
#pragma unroll
    for (int i = 0; i < 4; i++) {
        int l = l0 + ts + i;
        float pos = ((float)l + 0.5f) * LSCALE - 0.5f;
        pos = fminf(fmaxf(pos, 0.f), (float)(TFRAMES - 1));
        int i0 = (int)pos;
        int i1 = min(i0 + 1, TFRAMES - 1);
        float fw = pos - (float)i0;
        int fa = i0 - f0, fb = i1 - f0;
        float2 q01 = upk2(a2[0][i]), q23 = upk2(a2[1][i]);
        res[i] = q01.x * (sn[0 * 8 + fa] * (1.f - fw) + sn[0 * 8 + fb] * fw)
               + q01.y * (sn[1 * 8 + fa] * (1.f - fw) + sn[1 * 8 + fb] * fw)
               + q23.x * (sn[2 * 8 + fa] * (1.f - fw) + sn[2 * 8 + fb] * fw)
               + q23.y * (sn[3 * 8 + fa] * (1.f - fw) + sn[3 * 8 + fb] * fw);
    }
    *(float4*)&filt[(size_t)b * LSAMP + l0 + ts] = make_float4(res[0], res[1], res[2], res[3]);
}

// ---------------- filter bank + band mix + gate + outputs, f32x2 ----------------
#define STILE 512
__global__ void __launch_bounds__(128) shape_out2(const float* __restrict__ filt,
                                                  const float* __restrict__ fbw,
                                                  const float* __restrict__ band,
                                                  const float* __restrict__ attf,
                                                  const float* __restrict__ intf,
                                                  float* __restrict__ out, int write_gate) {
    __shared__ __align__(16) float swb[31 * 24];
    __shared__ float sx[STILE + 32];
    __shared__ float sgr[STILE + 4];
    __shared__ float sband[24 * 8];
    __shared__ float sia[16];
    const int b = blockIdx.y;
    const int l0 = blockIdx.x * STILE;
    const int tid = threadIdx.x;

    for (int i = tid; i < 31 * 24; i += 128) {
        int k = i / 24, bd = i - k * 24;
        swb[i] = fbw[bd * 31 + k];
    }
    for (int i = tid; i < STILE + 30; i += 128) {
        int l = l0 + i - 15;
        sx[i] = (l >= 0 && l < LSAMP) ? filt[(size_t)b * LSAMP + l] : 0.f;
    }
    const int fb0 = max(0, (int)floorf((l0 + 0.5f) * LSCALE - 0.5f));
    for (int i = tid; i < 24 * 8; i += 128) {
        int bd = i / 8, fi = i & 7;
        sband[i] = band[(size_t)(b * NB + bd) * TFRAMES + min(fb0 + fi, TFRAMES - 1)];
    }
    const int fg0 = max(0, (int)floorf((l0 - 2.5f) * LSCALE - 0.5f));
    if (tid < 16) {
        int fi = tid & 7;
        int fr = min(fg0 + fi, TFRAMES - 1);
        sia[tid] = (tid < 8) ? intf[b * TFRAMES + fr] : attf[b * TFRAMES + fr];
    }
    __syncthreads();

    for (int i = tid; i < STILE + 4; i += 128) {
        int j = l0 + i - 2;
        if (j < 0) j = -j;
        if (j > LSAMP - 1) j = 2 * (LSAMP - 1) - j;
        float il = lin1s(sia, j, fg0);
        float diff = (j == 0) ? 0.f : (il - lin1s(sia, j - 1, fg0));
        float gv = il;
        if (diff > 0.f) {
            float e = il;
            if (diff > 0.1f) e += lin1s(&sia[8], j, fg0) * 0.3f;
            gv = fminf(fmaxf(e, 0.f), 1.f);
        }
        sgr[i] = gv;
    }
    __syncthreads();

    const int ts = tid * 4;
    float fw4[4];
    int fiA[4], fiB[4];
#pragma unroll
    for (int i = 0; i < 4; i++) {
        int l = l0 + ts + i;
        float pos = ((float)l + 0.5f) * LSCALE - 0.5f;
        pos = fminf(fmaxf(pos, 0.f), (float)(TFRAMES - 1));
        int i0 = (int)pos;
        int i1 = min(i0 + 1, TFRAMES - 1);
        fw4[i] = pos - (float)i0;
        fiA[i] = i0 - fb0;
        fiB[i] = i1 - fb0;
    }

    float shaped[4] = {0.f, 0.f, 0.f, 0.f};
#pragma unroll 1
    for (int g3 = 0; g3 < 3; g3++) {
        ull a2[4][4];  // [band-pair][sample]
#pragma unroll
        for (int p = 0; p < 4; p++)
#pragma unroll
            for (int i = 0; i < 4; i++) a2[p][i] = 0ull;
        ull xd0 = dup2(sx[ts]), xd1 = dup2(sx[ts + 1]), xd2 = dup2(sx[ts + 2]), xd3;
#pragma unroll
        for (int k = 0; k < 31; k++) {
            xd3 = dup2(sx[ts + k + 3]);
            const ull* wr = (const ull*)&swb[k * 24 + g3 * 8];
            ull wp0 = wr[0], wp1 = wr[1], wp2 = wr[2], wp3 = wr[3];
            fma2(a2[0][0], wp0, xd0); fma2(a2[0][1], wp0, xd1);
            fma2(a2[0][2], wp0, xd2); fma2(a2[0][3], wp0, xd3);
            fma2(a2[1][0], wp1, xd0); fma2(a2[1][1], wp1, xd1);
            fma2(a2[1][2], wp1, xd2); fma2(a2[1][3], wp1, xd3);
            fma2(a2[2][0], wp2, xd0); fma2(a2[2][1], wp2, xd1);
            fma2(a2[2][2], wp2, xd2); fma2(a2[2][3], wp2, xd3);
            fma2(a2[3][0], wp3, xd0); fma2(a2[3][1], wp3, xd1);
            fma2(a2[3][2], wp3, xd2); fma2(a2[3][3], wp3, xd3);
            xd0 = xd1; xd1 = xd2; xd2 = xd3;
        }
#pragma unroll
        for (int p = 0; p < 4; p++) {
            const float* sbA = &sband[(g3 * 8 + 2 * p) * 8];
            const float* sbB = sbA + 8;
#pragma unroll
            for (int i = 0; i < 4; i++) {
                float2 q = upk2(a2[p][i]);
                float ampA = sbA[fiA[i]] * (1.f - fw4[i]) + sbA[fiB[i]] * fw4[i];
                float ampB = sbB[fiA[i]] * (1.f - fw4[i]) + sbB[fiB[i]] * fw4[i];
                shaped[i] += q.x * ampA + q.y * ampB;
            }
        }
    }

    float s[8];
#pragma unroll
    for (int ii = 0; ii < 8; ii++) s[ii] = sgr[ts + ii];
    float gv0 = 0.2f * (s[0] + s[1] + s[2] + s[3] + s[4]);
    float gv1 = 0.2f * (s[1] + s[2] + s[3] + s[4] + s[5]);
    float gv2 = 0.2f * (s[2] + s[3] + s[4] + s[5] + s[6]);
    float gv3 = 0.2f * (s[3] + s[4] + s[5] + s[6] + s[7]);
    *(float4*)&out[(size_t)b * LSAMP + l0 + ts] =
        make_float4(shaped[0] * gv0, shaped[1] * gv1, shaped[2] * gv2, shaped[3] * gv3);
    if (write_gate)
        *(float4*)&out[(size_t)BATCH * LSAMP + (size_t)b * LSAMP + l0 + ts] =
            make_float4(gv0, gv1, gv2, gv3);
}

// ---------------- launch ----------------
extern "C" void kernel_launch(void* const* d_in, const int* in_sizes, int n_in,
                              void* d_out, int out_size) {
    const float* cond  = (const float*)d_in[0];
    const float* wn    = (const float*)d_in[1];
    const float* np_w1 = (const float*)d_in[2];
    const float* np_b1 = (const float*)d_in[3];
    const float* np_w2 = (const float*)d_in[4];
    const float* np_b2 = (const float*)d_in[5];
    const float* np_w3 = (const float*)d_in[6];
    const float* np_b3 = (const float*)d_in[7];
    const float* ss_w1 = (const float*)d_in[8];
    const float* ss_b1 = (const float*)d_in[9];
    const float* ss_w2 = (const float*)d_in[10];
    const float* ss_b2 = (const float*)d_in[11];
    const float* fb_w  = (const float*)d_in[12];
    const float* nt_w  = (const float*)d_in[13];
    float* out = (float*)d_out;

    void *p_h1, *p_h2, *p_band, *p_att, *p_int, *p_ssg, *p_ntw, *p_filt;
    void *p_wt1, *p_wt2, *p_wts, *p_w3t, *p_w2t;
    cudaGetSymbolAddress(&p_h1, g_h1);
    cudaGetSymbolAddress(&p_h2, g_h2);
    cudaGetSymbolAddress(&p_band, g_band);
    cudaGetSymbolAddress(&p_att, g_att);
    cudaGetSymbolAddress(&p_int, g_int);
    cudaGetSymbolAddress(&p_ssg, g_ssg);
    cudaGetSymbolAddress(&p_ntw, g_ntw);
    cudaGetSymbolAddress(&p_filt, g_filt);
    cudaGetSymbolAddress(&p_wt1, g_wt1);
    cudaGetSymbolAddress(&p_wt2, g_wt2);
    cudaGetSymbolAddress(&p_wts, g_wts);
    cudaGetSymbolAddress(&p_w3t, g_w3t);
    cudaGetSymbolAddress(&p_w2t, g_w2t);

    int write_gate = (out_size >= 2 * BATCH * LSAMP) ? 1 : 0;

    prep_weights<<<296, 256>>>(np_w1, np_w2, ss_w1, np_w3, ss_w2,
                               (float*)p_wt1, (float*)p_wt2, (float*)p_wts,
                               (float*)p_w3t, (float*)p_w2t);

    conv3t<128, 256><<<dim3(13, 4, BATCH), 256>>>(cond, (const float*)p_wt1, np_b1, (float*)p_h1);
    conv3t<256, 256><<<dim3(13, 4, BATCH), 256>>>((const float*)p_h1, (const float*)p_wt2, np_b2, (float*)p_h2);
    np_head2<<<dim3(7, BATCH), 128>>>((const float*)p_h2, (const float*)p_w3t, np_b3,
                                      (float*)p_band, (float*)p_att, (float*)p_int);
    conv3t<128, 128><<<dim3(13, 2, BATCH), 256>>>(cond, (const float*)p_wts, ss_b1, (float*)p_ssg);
    ss_head2<<<25, 256>>>((const float*)p_ssg, (const float*)p_w2t, ss_b2, (float*)p_ntw);
    mix_noise2<<<dim3(LSAMP / MTILE, BATCH), 128>>>(wn, (const float*)p_ntw, nt_w, (float*)p_filt);
    shape_out2<<<dim3(LSAMP / STILE, BATCH), 128>>>((const float*)p_filt, fb_w,
                                                    (const float*)p_band, (const float*)p_att,
                                                    (const float*)p_int, out, write_gate);
}

// round 4
// speedup vs baseline: 3.2544x; 1.1870x over previous
#include <cuda_runtime.h>
#include <cuda_bf16.h>
#include <math.h>

#define BATCH 8
#define HID 128
#define TFRAMES 800
#define LSAMP 192000
#define NB 24
#define LSCALE ((float)(800.0 / 192000.0))

typedef unsigned long long ull;

// ---- packed fp32x2 helpers ----
__device__ __forceinline__ ull pk2(float lo, float hi) {
    ull r; asm("mov.b64 %0, {%1, %2};" : "=l"(r) : "f"(lo), "f"(hi)); return r;
}
__device__ __forceinline__ ull dup2(float v) {
    ull r; asm("mov.b64 %0, {%1, %1};" : "=l"(r) : "f"(v)); return r;
}
__device__ __forceinline__ void fma2(ull& acc, ull a, ull b) {
    asm("fma.rn.f32x2 %0, %1, %2, %0;" : "+l"(acc) : "l"(a), "l"(b));
}
__device__ __forceinline__ float2 upk2(ull v) {
    float2 f; asm("mov.b64 {%0, %1}, %2;" : "=f"(f.x), "=f"(f.y) : "l"(v)); return f;
}

// ---------------- scratch ----------------
__device__ float g_h1[BATCH * 256 * TFRAMES];
__device__ float g_h2[BATCH * 256 * TFRAMES];
__device__ float g_band[BATCH * NB * TFRAMES];
__device__ float g_att[BATCH * TFRAMES];
__device__ float g_int[BATCH * TFRAMES];
__device__ float g_ssg[BATCH * HID * TFRAMES];
__device__ float g_ntw[BATCH * 4 * TFRAMES];
__device__ float g_filt[BATCH * LSAMP];
__device__ float g_wt1[128 * 3 * 256];
__device__ float g_wt2[256 * 3 * 256];
__device__ float g_wts[128 * 3 * 128];
__device__ float g_w3t[256 * 28];
__device__ float g_w2t[128 * 4];

// ---------------- fused weight prep ----------------
__global__ void prep_weights(const float* __restrict__ w1, const float* __restrict__ w2,
                             const float* __restrict__ ws, const float* __restrict__ w3,
                             const float* __restrict__ wss2,
                             float* __restrict__ wt1, float* __restrict__ wt2,
                             float* __restrict__ wts, float* __restrict__ w3t,
                             float* __restrict__ w2t) {
    const int N1 = 256 * 128 * 3, N2 = 256 * 256 * 3, NS = 128 * 128 * 3;
    const int N3 = 256 * 28, N4 = 128 * 4;
    int total = N1 + N2 + NS + N3 + N4;
    for (int idx = blockIdx.x * blockDim.x + threadIdx.x; idx < total;
         idx += gridDim.x * blockDim.x) {
        int i = idx;
        if (i < N1) {
            int co = i / (128 * 3), rem = i - co * (128 * 3);
            wt1[rem * 256 + co] = w1[i];
        } else if ((i -= N1) < N2) {
            int co = i / (256 * 3), rem = i - co * (256 * 3);
            wt2[rem * 256 + co] = w2[i];
        } else if ((i -= N2) < NS) {
            int co = i / (128 * 3), rem = i - co * (128 * 3);
            wts[rem * 128 + co] = ws[i];
        } else if ((i -= NS) < N3) {
            int ci = i / 28, co = i - ci * 28;
            w3t[i] = (co < 27) ? w3[co * 256 + ci] : 0.f;
        } else {
            i -= N3;
            int ci = i / 4, f = i - ci * 4;
            w2t[i] = wss2[f * 128 + ci];
        }
    }
}

// ---------------- K=3 conv + leaky_relu, GEMM-style, f32x2 ----------------
template <int CIN, int COUT>
__global__ void __launch_bounds__(256) conv3t(const float* __restrict__ x,
                                              const float* __restrict__ wt,
                                              const float* __restrict__ bias,
                                              float* __restrict__ y) {
    __shared__ __align__(16) float sx[32][68];
    __shared__ __align__(16) float swf[96 * 64];
    const int tid = threadIdx.x;
    const int cx = tid & 15, tx = tid >> 4;
    const int t_base = tx * 4, co_base = cx * 4;
    const int b = blockIdx.z, c0 = blockIdx.y * 64, t0 = blockIdx.x * 64;

    ull acc[2][4];
    {
        const float4 bv = *(const float4*)&bias[c0 + co_base];
        ull p0 = pk2(bv.x, bv.y), p1 = pk2(bv.z, bv.w);
#pragma unroll
        for (int i = 0; i < 4; i++) { acc[0][i] = p0; acc[1][i] = p1; }
    }

    for (int ci0 = 0; ci0 < CIN; ci0 += 32) {
#pragma unroll 1
        for (int idx = tid; idx < 32 * 66; idx += 256) {
            int kc = idx / 66, i = idx - kc * 66;
            int t = t0 + i - 1;
            sx[kc][i] = (t >= 0 && t < TFRAMES)
                            ? x[((size_t)(b * CIN + ci0 + kc)) * TFRAMES + t] : 0.f;
        }
#pragma unroll 1
        for (int idx = tid; idx < 6144; idx += 256) {
            swf[idx] = wt[(size_t)(ci0 * 3 + (idx >> 6)) * COUT + c0 + (idx & 63)];
        }
        __syncthreads();
#pragma unroll 4
        for (int kc = 0; kc < 32; kc++) {
            const float* xr = &sx[kc][t_base];
            float4 xa = *(const float4*)xr;
            float2 xb = *(const float2*)(xr + 4);
            ull xd[6];
            xd[0] = dup2(xa.x); xd[1] = dup2(xa.y); xd[2] = dup2(xa.z);
            xd[3] = dup2(xa.w); xd[4] = dup2(xb.x); xd[5] = dup2(xb.y);
            const ull* w0 = (const ull*)&swf[kc * 192 + co_base];
            const ull* w1 = (const ull*)&swf[kc * 192 + 64 + co_base];
            const ull* w2 = (const ull*)&swf[kc * 192 + 128 + co_base];
#pragma unroll
            for (int jp = 0; jp < 2; jp++) {
                ull wa = w0[jp], wb = w1[jp], wc = w2[jp];
#pragma unroll
                for (int i = 0; i < 4; i++) {
                    fma2(acc[jp][i], wa, xd[i]);
                    fma2(acc[jp][i], wb, xd[i + 1]);
                    fma2(acc[jp][i], wc, xd[i + 2]);
                }
            }
        }
        __syncthreads();
    }

    const int t_out = t0 + t_base;
#pragma unroll
    for (int jp = 0; jp < 2; jp++) {
        float vlo[4], vhi[4];
#pragma unroll
        for (int i = 0; i < 4; i++) {
            float2 f = upk2(acc[jp][i]);
            vlo[i] = f.x > 0.f ? f.x : 0.1f * f.x;
            vhi[i] = f.y > 0.f ? f.y : 0.1f * f.y;
        }
        float* yr0 = y + ((size_t)(b * COUT + c0 + co_base + jp * 2)) * TFRAMES + t_out;
        float* yr1 = yr0 + TFRAMES;
        if (t_out + 3 < TFRAMES) {
            *(float4*)yr0 = make_float4(vlo[0], vlo[1], vlo[2], vlo[3]);
            *(float4*)yr1 = make_float4(vhi[0], vhi[1], vhi[2], vhi[3]);
        } else {
#pragma unroll
            for (int i = 0; i < 4; i++)
                if (t_out + i < TFRAMES) { yr0[i] = vlo[i]; yr1[i] = vhi[i]; }
        }
    }
}

// ---------------- noise-predictor head: split-channel, shfl reduce ----------------
// warp: 4 channel-groups x 8 t. block 256 = 8 warps = 64 t. grid (13, 8).
__global__ void __launch_bounds__(256) np_head3(const float* __restrict__ h2,
                                                const float* __restrict__ w3t,
                                                const float* __restrict__ b3,
                                                float* __restrict__ band,
                                                float* __restrict__ att,
                                                float* __restrict__ inten) {
    __shared__ __align__(16) float swh[256 * 28];
    const int tid = threadIdx.x;
    // interleave channel-groups so concurrent cg reads hit distinct banks:
    // swh[(i*4+cg)*28 + q] = w3t[(cg*64+i)*28 + q]
    for (int idx = tid; idx < 256 * 28; idx += 256) {
        int ci = idx / 28, q = idx - ci * 28;
        int i = ci & 63, cg = ci >> 6;
        swh[(i * 4 + cg) * 28 + q] = w3t[idx];
    }
    __syncthreads();

    const int lane = tid & 31, warp = tid >> 5;
    const int cg = lane >> 3, tsub = lane & 7;
    const int b = blockIdx.y;
    const int t = blockIdx.x * 64 + warp * 8 + tsub;
    const int tc = min(t, TFRAMES - 1);

    ull acc[14];
#pragma unroll
    for (int q = 0; q < 14; q++) acc[q] = 0ull;

    const float* xp = h2 + ((size_t)(b * 256 + cg * 64)) * TFRAMES + tc;
#pragma unroll 8
    for (int i = 0; i < 64; i++) {
        ull xd = dup2(__ldg(xp + (size_t)i * TFRAMES));
        const ull* wr = (const ull*)&swh[(i * 4 + cg) * 28];
#pragma unroll
        for (int q = 0; q < 14; q++) fma2(acc[q], wr[q], xd);
    }

    float r[28];
#pragma unroll
    for (int q = 0; q < 14; q++) {
        float2 f = upk2(acc[q]);
        r[2 * q] = f.x; r[2 * q + 1] = f.y;
    }
#pragma unroll
    for (int q = 0; q < 28; q++) {
        r[q] += __shfl_xor_sync(0xffffffffu, r[q], 8);
        r[q] += __shfl_xor_sync(0xffffffffu, r[q], 16);
    }
    if (cg == 0 && t < TFRAMES) {
        float* bb = band + (size_t)b * NB * TFRAMES + t;
#pragma unroll
        for (int co = 0; co < NB; co++)
            bb[(size_t)co * TFRAMES] = 1.f / (1.f + expf(-(r[co] + b3[co])));
        att[b * TFRAMES + t] = 10.f / (1.f + expf(-(r[24] + b3[24])));
        inten[b * TFRAMES + t] = 1.f / (1.f + expf(-(r[26] + b3[26])));
    }
}

// ---------------- spectral-shaper head: 128 -> 4 + softmax ----------------
__global__ void ss_head2(const float* __restrict__ g, const float* __restrict__ w2t,
                         const float* __restrict__ b2, float* __restrict__ ntw) {
    __shared__ __align__(16) float sw[512];
    const int tid = threadIdx.x;
    for (int i = tid; i < 512; i += 256) sw[i] = w2t[i];
    __syncthreads();
    int idx = blockIdx.x * 256 + tid;
    if (idx >= BATCH * TFRAMES) return;
    int b = idx / TFRAMES, t = idx - b * TFRAMES;
    ull a01 = pk2(b2[0], b2[1]), a23 = pk2(b2[2], b2[3]);
    const float* gb = g + (size_t)b * HID * TFRAMES + t;
#pragma unroll 8
    for (int ci = 0; ci < HID; ci++) {
        ull xd = dup2(__ldg(gb + (size_t)ci * TFRAMES));
        const ull* wr = (const ull*)&sw[ci * 4];
        fma2(a01, wr[0], xd);
        fma2(a23, wr[1], xd);
    }
    float2 f01 = upk2(a01), f23 = upk2(a23);
    float m = fmaxf(fmaxf(f01.x, f01.y), fmaxf(f23.x, f23.y));
    float e0 = expf(f01.x - m), e1 = expf(f01.y - m);
    float e2 = expf(f23.x - m), e3 = expf(f23.y - m);
    float inv = 1.f / (e0 + e1 + e2 + e3);
    ntw[(size_t)(b * 4 + 0) * TFRAMES + t] = e0 * inv;
    ntw[(size_t)(b * 4 + 1) * TFRAMES + t] = e1 * inv;
    ntw[(size_t)(b * 4 + 2) * TFRAMES + t] = e2 * inv;
    ntw[(size_t)(b * 4 + 3) * TFRAMES + t] = e3 * inv;
}

__device__ __forceinline__ float lin1s(const float* __restrict__ s, int j, int f0) {
    float pos = ((float)j + 0.5f) * LSCALE - 0.5f;
    pos = fminf(fmaxf(pos, 0.f), (float)(TFRAMES - 1));
    int i0 = (int)pos;
    int i1 = min(i0 + 1, TFRAMES - 1);
    float fw = pos - (float)i0;
    return s[i0 - f0] * (1.f - fw) + s[i1 - f0] * fw;
}

// ---------------- noise-type filtering + mixing, f32x2 ----------------
#define MTILE 512
__global__ void __launch_bounds__(128) mix_noise2(const float* __restrict__ wn,
                                                  const float* __restrict__ ntwf,
                                                  const float* __restrict__ ntw_w,
                                                  float* __restrict__ filt) {
    __shared__ __align__(16) float sw4[63 * 4];
    __shared__ float sx[MTILE + 64];
    __shared__ float sn[4 * 8];
    const int b = blockIdx.y;
    const int l0 = blockIdx.x * MTILE;
    const int tid = threadIdx.x;

    for (int i = tid; i < 252; i += 128) {
        int f = i / 63, k = i - f * 63;
        sw4[k * 4 + f] = ntw_w[i];
    }
    for (int i = tid; i < MTILE + 62; i += 128) {
        int l = l0 + i - 31;
        sx[i] = (l >= 0 && l < LSAMP) ? wn[(size_t)b * LSAMP + l] : 0.f;
    }
    const int f0 = max(0, (int)floorf((l0 + 0.5f) * LSCALE - 0.5f));
    if (tid < 32) {
        int f = tid / 8, fi = tid & 7;
        sn[tid] = ntwf[(size_t)(b * 4 + f) * TFRAMES + min(f0 + fi, TFRAMES - 1)];
    }
    __syncthreads();

    const int ts = tid * 4;
    ull a2[2][4];
#pragma unroll
    for (int p = 0; p < 2; p++)
#pragma unroll
        for (int i = 0; i < 4; i++) a2[p][i] = 0ull;

    ull xd0 = dup2(sx[ts]), xd1 = dup2(sx[ts + 1]), xd2 = dup2(sx[ts + 2]), xd3;
#pragma unroll 7
    for (int k = 0; k < 63; k++) {
        xd3 = dup2(sx[ts + k + 3]);
        const ull* wr = (const ull*)&sw4[k * 4];
        ull w01 = wr[0], w23 = wr[1];
        fma2(a2[0][0], w01, xd0); fma2(a2[0][1], w01, xd1);
        fma2(a2[0][2], w01, xd2); fma2(a2[0][3], w01, xd3);
        fma2(a2[1][0], w23, xd0); fma2(a2[1][1], w23, xd1);
        fma2(a2[1][2], w23, xd2); fma2(a2[1][3], w23, xd3);
        xd0 = xd1; xd1 = xd2; xd2 = xd3;
    }
    float res[4];
#pragma unroll
    for (int i = 0; i < 4; i++) {
        int l = l0 + ts + i;
        float pos = ((float)l + 0.5f) * LSCALE - 0.5f;
        pos = fminf(fmaxf(pos, 0.f), (float)(TFRAMES - 1));
        int i0 = (int)pos;
        int i1 = min(i0 + 1, TFRAMES - 1);
        float fw = pos - (float)i0;
        int fa = i0 - f0, fb = i1 - f0;
        float2 q01 = upk2(a2[0][i]), q23 = upk2(a2[1][i]);
        res[i] = q01.x * (sn[0 * 8 + fa] * (1.f - fw) + sn[0 * 8 + fb] * fw)
               + q01.y * (sn[1 * 8 + fa] * (1.f - fw) + sn[1 * 8 + fb] * fw)
               + q23.x * (sn[2 * 8 + fa] * (1.f - fw) + sn[2 * 8 + fb] * fw)
               + q23.y * (sn[3 * 8 + fa] * (1.f - fw) + sn[3 * 8 + fb] * fw);
    }
    *(float4*)&filt[(size_t)b * LSAMP + l0 + ts] = make_float4(res[0], res[1], res[2], res[3]);
}

// ---------------- filter bank + band mix + gate + outputs, f32x2 ----------------
#define STILE 512
__global__ void __launch_bounds__(128) shape_out2(const float* __restrict__ filt,
                                                  const float* __restrict__ fbw,
                                                  const float* __restrict__ band,
                                                  const float* __restrict__ attf,
                                                  const float* __restrict__ intf,
                                                  float* __restrict__ out, int write_gate) {
    __shared__ __align__(16) float swb[31 * 24];
    __shared__ float sx[STILE + 32];
    __shared__ float sgr[STILE + 4];
    __shared__ float sband[24 * 8];
    __shared__ float sia[16];
    const int b = blockIdx.y;
    const int l0 = blockIdx.x * STILE;
    const int tid = threadIdx.x;

    for (int i = tid; i < 31 * 24; i += 128) {
        int k = i / 24, bd = i - k * 24;
        swb[i] = fbw[bd * 31 + k];
    }
    for (int i = tid; i < STILE + 30; i += 128) {
        int l = l0 + i - 15;
        sx[i] = (l >= 0 && l < LSAMP) ? filt[(size_t)b * LSAMP + l] : 0.f;
    }
    const int fb0 = max(0, (int)floorf((l0 + 0.5f) * LSCALE - 0.5f));
    for (int i = tid; i < 24 * 8; i += 128) {
        int bd = i / 8, fi = i & 7;
        sband[i] = band[(size_t)(b * NB + bd) * TFRAMES + min(fb0 + fi, TFRAMES - 1)];
    }
    const int fg0 = max(0, (int)floorf((l0 - 2.5f) * LSCALE - 0.5f));
    if (tid < 16) {
        int fi = tid & 7;
        int fr = min(fg0 + fi, TFRAMES - 1);
        sia[tid] = (tid < 8) ? intf[b * TFRAMES + fr] : attf[b * TFRAMES + fr];
    }
    __syncthreads();

    for (int i = tid; i < STILE + 4; i += 128) {
        int j = l0 + i - 2;
        if (j < 0) j = -j;
        if (j > LSAMP - 1) j = 2 * (LSAMP - 1) - j;
        float il = lin1s(sia, j, fg0);
        float diff = (j == 0) ? 0.f : (il - lin1s(sia, j - 1, fg0));
        float gv = il;
        if (diff > 0.f) {
            float e = il;
            if (diff > 0.1f) e += lin1s(&sia[8], j, fg0) * 0.3f;
            gv = fminf(fmaxf(e, 0.f), 1.f);
        }
        sgr[i] = gv;
    }
    __syncthreads();

    const int ts = tid * 4;
    float fw4[4];
    int fiA[4], fiB[4];
#pragma unroll
    for (int i = 0; i < 4; i++) {
        int l = l0 + ts + i;
        float pos = ((float)l + 0.5f) * LSCALE - 0.5f;
        pos = fminf(fmaxf(pos, 0.f), (float)(TFRAMES - 1));
        int i0 = (int)pos;
        int i1 = min(i0 + 1, TFRAMES - 1);
        fw4[i] = pos - (float)i0;
        fiA[i] = i0 - fb0;
        fiB[i] = i1 - fb0;
    }

    float shaped[4] = {0.f, 0.f, 0.f, 0.f};
#pragma unroll 1
    for (int g3 = 0; g3 < 3; g3++) {
        ull a2[4][4];
#pragma unroll
        for (int p = 0; p < 4; p++)
#pragma unroll
            for (int i = 0; i < 4; i++) a2[p][i] = 0ull;
        ull xd0 = dup2(sx[ts]), xd1 = dup2(sx[ts + 1]), xd2 = dup2(sx[ts + 2]), xd3;
#pragma unroll
        for (int k = 0; k < 31; k++) {
            xd3 = dup2(sx[ts + k + 3]);
            const ull* wr = (const ull*)&swb[k * 24 + g3 * 8];
            ull wp0 = wr[0], wp1 = wr[1], wp2 = wr[2], wp3 = wr[3];
            fma2(a2[0][0], wp0, xd0); fma2(a2[0][1], wp0, xd1);
            fma2(a2[0][2], wp0, xd2); fma2(a2[0][3], wp0, xd3);
            fma2(a2[1][0], wp1, xd0); fma2(a2[1][1], wp1, xd1);
            fma2(a2[1][2], wp1, xd2); fma2(a2[1][3], wp1, xd3);
            fma2(a2[2][0], wp2, xd0); fma2(a2[2][1], wp2, xd1);
            fma2(a2[2][2], wp2, xd2); fma2(a2[2][3], wp2, xd3);
            fma2(a2[3][0], wp3, xd0); fma2(a2[3][1], wp3, xd1);
            fma2(a2[3][2], wp3, xd2); fma2(a2[3][3], wp3, xd3);
            xd0 = xd1; xd1 = xd2; xd2 = xd3;
        }
#pragma unroll
        for (int p = 0; p < 4; p++) {
            const float* sbA = &sband[(g3 * 8 + 2 * p) * 8];
            const float* sbB = sbA + 8;
#pragma unroll
            for (int i = 0; i < 4; i++) {
                float2 q = upk2(a2[p][i]);
                float ampA = sbA[fiA[i]] * (1.f - fw4[i]) + sbA[fiB[i]] * fw4[i];
                float ampB = sbB[fiA[i]] * (1.f - fw4[i]) + sbB[fiB[i]] * fw4[i];
                shaped[i] += q.x * ampA + q.y * ampB;
            }
        }
    }

    float s[8];
#pragma unroll
    for (int ii = 0; ii < 8; ii++) s[ii] = sgr[ts + ii];
    float gv0 = 0.2f * (s[0] + s[1] + s[2] + s[3] + s[4]);
    float gv1 = 0.2f * (s[1] + s[2] + s[3] + s[4] + s[5]);
    float gv2 = 0.2f * (s[2] + s[3] + s[4] + s[5] + s[6]);
    float gv3 = 0.2f * (s[3] + s[4] + s[5] + s[6] + s[7]);
    *(float4*)&out[(size_t)b * LSAMP + l0 + ts] =
        make_float4(shaped[0] * gv0, shaped[1] * gv1, shaped[2] * gv2, shaped[3] * gv3);
    if (write_gate)
        *(float4*)&out[(size_t)BATCH * LSAMP + (size_t)b * LSAMP + l0 + ts] =
            make_float4(gv0, gv1, gv2, gv3);
}

// ---------------- launch (fork-join stream overlap) ----------------
extern "C" void kernel_launch(void* const* d_in, const int* in_sizes, int n_in,
                              void* d_out, int out_size) {
    const float* cond  = (const float*)d_in[0];
    const float* wn    = (const float*)d_in[1];
    const float* np_w1 = (const float*)d_in[2];
    const float* np_b1 = (const float*)d_in[3];
    const float* np_w2 = (const float*)d_in[4];
    const float* np_b2 = (const float*)d_in[5];
    const float* np_w3 = (const float*)d_in[6];
    const float* np_b3 = (const float*)d_in[7];
    const float* ss_w1 = (const float*)d_in[8];
    const float* ss_b1 = (const float*)d_in[9];
    const float* ss_w2 = (const float*)d_in[10];
    const float* ss_b2 = (const float*)d_in[11];
    const float* fb_w  = (const float*)d_in[12];
    const float* nt_w  = (const float*)d_in[13];
    float* out = (float*)d_out;

    void *p_h1, *p_h2, *p_band, *p_att, *p_int, *p_ssg, *p_ntw, *p_filt;
    void *p_wt1, *p_wt2, *p_wts, *p_w3t, *p_w2t;
    cudaGetSymbolAddress(&p_h1, g_h1);
    cudaGetSymbolAddress(&p_h2, g_h2);
    cudaGetSymbolAddress(&p_band, g_band);
    cudaGetSymbolAddress(&p_att, g_att);
    cudaGetSymbolAddress(&p_int, g_int);
    cudaGetSymbolAddress(&p_ssg, g_ssg);
    cudaGetSymbolAddress(&p_ntw, g_ntw);
    cudaGetSymbolAddress(&p_filt, g_filt);
    cudaGetSymbolAddress(&p_wt1, g_wt1);
    cudaGetSymbolAddress(&p_wt2, g_wt2);
    cudaGetSymbolAddress(&p_wts, g_wts);
    cudaGetSymbolAddress(&p_w3t, g_w3t);
    cudaGetSymbolAddress(&p_w2t, g_w2t);

    static cudaStream_t s2 = nullptr;
    static cudaEvent_t ev_fork = nullptr, ev_join = nullptr;
    if (s2 == nullptr) {
        cudaStreamCreateWithFlags(&s2, cudaStreamNonBlocking);
        cudaEventCreateWithFlags(&ev_fork, cudaEventDisableTiming);
        cudaEventCreateWithFlags(&ev_join, cudaEventDisableTiming);
    }

    int write_gate = (out_size >= 2 * BATCH * LSAMP) ? 1 : 0;

    prep_weights<<<296, 256>>>(np_w1, np_w2, ss_w1, np_w3, ss_w2,
                               (float*)p_wt1, (float*)p_wt2, (float*)p_wts,
                               (float*)p_w3t, (float*)p_w2t);
    cudaEventRecord(ev_fork, 0);
    cudaStreamWaitEvent(s2, ev_fork, 0);

    // side branch: spectral shaper -> softmax -> noise-type mix
    conv3t<128, 128><<<dim3(13, 2, BATCH), 256, 0, s2>>>(cond, (const float*)p_wts, ss_b1,
                                                          (float*)p_ssg);
    ss_head2<<<25, 256, 0, s2>>>((const float*)p_ssg, (const float*)p_w2t, ss_b2, (float*)p_ntw);
    mix_noise2<<<dim3(LSAMP / MTILE, BATCH), 128, 0, s2>>>(wn, (const float*)p_ntw, nt_w,
                                                           (float*)p_filt);
    cudaEventRecord(ev_join, s2);

    // main branch: noise predictor
    conv3t<128, 256><<<dim3(13, 4, BATCH), 256>>>(cond, (const float*)p_wt1, np_b1, (float*)p_h1);
    conv3t<256, 256><<<dim3(13, 4, BATCH), 256>>>((const float*)p_h1, (const float*)p_wt2, np_b2,
                                                  (float*)p_h2);
    np_head3<<<dim3(13, BATCH), 256>>>((const float*)p_h2, (const float*)p_w3t, np_b3,
                                       (float*)p_band, (float*)p_att, (float*)p_int);

    cudaStreamWaitEvent(0, ev_join, 0);
    shape_out2<<<dim3(LSAMP / STILE, BATCH), 128>>>((const float*)p_filt, fb_w,
                                                    (const float*)p_band, (const float*)p_att,
                                                    (const float*)p_int, out, write_gate);
}